// round 1
// baseline (speedup 1.0000x reference)
#include <cuda_runtime.h>
#include <cuda_fp16.h>
#include <mma.h>

using namespace nvcuda;

// Problem shapes (fixed by the dataset)
#define IN_F   4096
#define OUT_F  4096
#define RANK   64

// Persistent scratch (no cudaMalloc allowed)
__device__ __half g_win[RANK * IN_F];    // soft-thresholded, scaled weight_in  [64][4096]
__device__ __half g_wout[OUT_F * RANK];  // soft-thresholded, scaled weight_out [4096][64]
__device__ __half g_xp[8192 * RANK];     // intermediate xp (f16, matching reference cast)

// ---------------------------------------------------------------------------
// Weight prep: 2:4 soft threshold along last dim (groups of 4) + scale + f16
// ---------------------------------------------------------------------------
__device__ __forceinline__ void soft_threshold4(float4 w, float s,
                                                float& o0, float& o1, float& o2, float& o3) {
    float m0 = fabsf(w.x), m1 = fabsf(w.y), m2 = fabsf(w.z), m3 = fabsf(w.w);
    float lo01 = fminf(m0, m1), hi01 = fmaxf(m0, m1);
    float lo23 = fminf(m2, m3), hi23 = fmaxf(m2, m3);
    // second-smallest of {m0..m3}
    float t = fminf(fmaxf(lo01, lo23), fminf(hi01, hi23));
    o0 = copysignf(fmaxf(m0 - t, 0.0f), w.x) * s;
    o1 = copysignf(fmaxf(m1 - t, 0.0f), w.y) * s;
    o2 = copysignf(fmaxf(m2 - t, 0.0f), w.z) * s;
    o3 = copysignf(fmaxf(m3 - t, 0.0f), w.w) * s;
}

__global__ void prep_weights_kernel(const float* __restrict__ win,
                                    const float* __restrict__ wout,
                                    const float* __restrict__ scale_in,
                                    const float* __restrict__ scale_out) {
    const int NGI = RANK * IN_F / 4;   // 65536 groups in weight_in
    const int NGO = OUT_F * RANK / 4;  // 65536 groups in weight_out
    int idx = blockIdx.x * blockDim.x + threadIdx.x;
    if (idx < NGI) {
        float4 w = reinterpret_cast<const float4*>(win)[idx];
        float o0, o1, o2, o3;
        soft_threshold4(w, *scale_in, o0, o1, o2, o3);
        __half2* dst = reinterpret_cast<__half2*>(g_win) + idx * 2;
        dst[0] = __floats2half2_rn(o0, o1);
        dst[1] = __floats2half2_rn(o2, o3);
    } else if (idx < NGI + NGO) {
        int j = idx - NGI;
        float4 w = reinterpret_cast<const float4*>(wout)[j];
        float o0, o1, o2, o3;
        soft_threshold4(w, *scale_out, o0, o1, o2, o3);
        __half2* dst = reinterpret_cast<__half2*>(g_wout) + j * 2;
        dst[0] = __floats2half2_rn(o0, o1);
        dst[1] = __floats2half2_rn(o2, o3);
    }
}

// ---------------------------------------------------------------------------
// GEMM1: xp[m, r] = sum_k f16(x[m,k]) * g_win[r,k]   (M=8192, N=64, K=4096)
// Block tile: 64(M) x 64(N), K-chunk 64, 8 warps (4x2), warp tile 16x32.
// Register-prefetch pipeline over the K loop to hide DRAM latency on x.
// ---------------------------------------------------------------------------
#define G1_BM 64
#define G1_BK 64
#define G1_LDA 72   // half, padded (multiple of 8 for ldmatrix/wmma)
#define G1_LDC 68   // float, padded (multiple of 4)

__global__ __launch_bounds__(256, 1)
void gemm1_kernel(const float* __restrict__ x, int M) {
    extern __shared__ char smem_raw[];
    __half* As = reinterpret_cast<__half*>(smem_raw);                 // [64][72]
    __half* Bs = As + G1_BM * G1_LDA;                                 // [64][72]
    float*  Cs = reinterpret_cast<float*>(smem_raw);                  // [64][68] (reuse)

    const int tid  = threadIdx.x;
    const int warp = tid >> 5;
    const int wm   = warp & 3;   // 0..3 -> 16 rows each
    const int wn   = warp >> 2;  // 0..1 -> 32 cols each
    const int m0   = blockIdx.x * G1_BM;

    wmma::fragment<wmma::accumulator, 16, 16, 16, float> acc[2];
    wmma::fill_fragment(acc[0], 0.0f);
    wmma::fill_fragment(acc[1], 0.0f);

    const int NK = IN_F / G1_BK;  // 64

    // register staging for the pipeline
    float4 xa[4];
    int4   wb[2];

    auto load_regs = [&](int kt) {
        #pragma unroll
        for (int it = 0; it < 4; it++) {
            int i   = tid + it * 256;
            int row = i >> 4;            // 16 float4 per row of 64 floats
            int c4  = i & 15;
            xa[it] = *reinterpret_cast<const float4*>(
                &x[(size_t)(m0 + row) * IN_F + kt * G1_BK + c4 * 4]);
        }
        #pragma unroll
        for (int it = 0; it < 2; it++) {
            int i   = tid + it * 256;
            int row = i >> 3;            // 8 int4 (64 halves) per row
            int c8  = i & 7;
            wb[it] = *reinterpret_cast<const int4*>(
                &g_win[row * IN_F + kt * G1_BK + c8 * 8]);
        }
    };

    load_regs(0);

    for (int kt = 0; kt < NK; kt++) {
        // stage regs -> smem
        #pragma unroll
        for (int it = 0; it < 4; it++) {
            int i   = tid + it * 256;
            int row = i >> 4;
            int c4  = i & 15;
            __half* p = &As[row * G1_LDA + c4 * 4];
            reinterpret_cast<__half2*>(p)[0] = __floats2half2_rn(xa[it].x, xa[it].y);
            reinterpret_cast<__half2*>(p)[1] = __floats2half2_rn(xa[it].z, xa[it].w);
        }
        #pragma unroll
        for (int it = 0; it < 2; it++) {
            int i   = tid + it * 256;
            int row = i >> 3;
            int c8  = i & 7;
            *reinterpret_cast<int4*>(&Bs[row * G1_LDA + c8 * 8]) = wb[it];
        }
        __syncthreads();

        // prefetch next tile (overlaps with MMA below)
        if (kt + 1 < NK) load_regs(kt + 1);

        #pragma unroll
        for (int k4 = 0; k4 < 4; k4++) {
            wmma::fragment<wmma::matrix_a, 16, 16, 16, __half, wmma::row_major> a;
            wmma::load_matrix_sync(a, &As[(wm * 16) * G1_LDA + k4 * 16], G1_LDA);
            #pragma unroll
            for (int j = 0; j < 2; j++) {
                wmma::fragment<wmma::matrix_b, 16, 16, 16, __half, wmma::col_major> b;
                wmma::load_matrix_sync(b, &Bs[(wn * 32 + j * 16) * G1_LDA + k4 * 16], G1_LDA);
                wmma::mma_sync(acc[j], a, b, acc[j]);
            }
        }
        __syncthreads();
    }

    // stage accumulators to smem (f32), then convert+write xp (f16)
    #pragma unroll
    for (int j = 0; j < 2; j++)
        wmma::store_matrix_sync(&Cs[(wm * 16) * G1_LDC + wn * 32 + j * 16], acc[j],
                                G1_LDC, wmma::mem_row_major);
    __syncthreads();

    #pragma unroll
    for (int it = 0; it < 8; it++) {         // 64*32 half2 = 2048 / 256 threads
        int i   = tid + it * 256;
        int row = i >> 5;
        int c2  = i & 31;
        __half2 h = __floats2half2_rn(Cs[row * G1_LDC + c2 * 2],
                                      Cs[row * G1_LDC + c2 * 2 + 1]);
        reinterpret_cast<__half2*>(g_xp)[(size_t)(m0 + row) * (RANK / 2) + c2] = h;
    }
}

// ---------------------------------------------------------------------------
// GEMM2: out[m, o] = (sum_r xp[m,r] * g_wout[o,r] + bias[o]) * (1/64)
// Block tile: 64(M) x 128(N), K = 64 (whole rank), 8 warps (4x2), warp 16x64.
// ---------------------------------------------------------------------------
#define G2_BM 64
#define G2_BN 128
#define G2_LD 72    // half, padded
#define G2_LDC 132  // float, padded (multiple of 4)

__global__ __launch_bounds__(256, 1)
void gemm2_kernel(const float* __restrict__ bias, float* __restrict__ out, int M) {
    extern __shared__ char smem_raw[];
    __half* Ps = reinterpret_cast<__half*>(smem_raw);         // xp tile   [64][72]
    __half* Ws = Ps + G2_BM * G2_LD;                          // wout tile [128][72]
    float*  Cs = reinterpret_cast<float*>(smem_raw);          // [64][132] (reuse)

    const int tid  = threadIdx.x;
    const int warp = tid >> 5;
    const int wm   = warp & 3;   // 16 rows each
    const int wn   = warp >> 2;  // 64 cols each
    const int m0   = blockIdx.x * G2_BM;
    const int n0   = blockIdx.y * G2_BN;

    // load xp tile: 64 rows x 64 halves = 512 int4
    #pragma unroll
    for (int it = 0; it < 2; it++) {
        int i = tid + it * 256;
        int row = i >> 3, c8 = i & 7;
        *reinterpret_cast<int4*>(&Ps[row * G2_LD + c8 * 8]) =
            *reinterpret_cast<const int4*>(&g_xp[(size_t)(m0 + row) * RANK + c8 * 8]);
    }
    // load wout tile: 128 rows x 64 halves = 1024 int4
    #pragma unroll
    for (int it = 0; it < 4; it++) {
        int i = tid + it * 256;
        int row = i >> 3, c8 = i & 7;
        *reinterpret_cast<int4*>(&Ws[row * G2_LD + c8 * 8]) =
            *reinterpret_cast<const int4*>(&g_wout[(size_t)(n0 + row) * RANK + c8 * 8]);
    }
    __syncthreads();

    wmma::fragment<wmma::accumulator, 16, 16, 16, float> acc[4];
    #pragma unroll
    for (int j = 0; j < 4; j++) wmma::fill_fragment(acc[j], 0.0f);

    #pragma unroll
    for (int k4 = 0; k4 < 4; k4++) {
        wmma::fragment<wmma::matrix_a, 16, 16, 16, __half, wmma::row_major> a;
        wmma::load_matrix_sync(a, &Ps[(wm * 16) * G2_LD + k4 * 16], G2_LD);
        #pragma unroll
        for (int j = 0; j < 4; j++) {
            wmma::fragment<wmma::matrix_b, 16, 16, 16, __half, wmma::col_major> b;
            wmma::load_matrix_sync(b, &Ws[(wn * 64 + j * 16) * G2_LD + k4 * 16], G2_LD);
            wmma::mma_sync(acc[j], a, b, acc[j]);
        }
    }
    __syncthreads();

    #pragma unroll
    for (int j = 0; j < 4; j++)
        wmma::store_matrix_sync(&Cs[(wm * 16) * G2_LDC + wn * 64 + j * 16], acc[j],
                                G2_LDC, wmma::mem_row_major);
    __syncthreads();

    const float scaling = 1.0f / (float)RANK;
    // write 64 x 128 f32 = 2048 float4
    #pragma unroll
    for (int it = 0; it < 8; it++) {
        int i   = tid + it * 256;
        int row = i >> 5;
        int c4  = i & 31;
        float4 c  = *reinterpret_cast<float4*>(&Cs[row * G2_LDC + c4 * 4]);
        float4 bv = *reinterpret_cast<const float4*>(&bias[n0 + c4 * 4]);
        float4 o;
        o.x = (c.x + bv.x) * scaling;
        o.y = (c.y + bv.y) * scaling;
        o.z = (c.z + bv.z) * scaling;
        o.w = (c.w + bv.w) * scaling;
        *reinterpret_cast<float4*>(&out[(size_t)(m0 + row) * OUT_F + n0 + c4 * 4]) = o;
    }
}

// ---------------------------------------------------------------------------
// Launcher
// ---------------------------------------------------------------------------
extern "C" void kernel_launch(void* const* d_in, const int* in_sizes, int n_in,
                              void* d_out, int out_size) {
    const float* x         = (const float*)d_in[0];
    const float* weight_in = (const float*)d_in[1];
    const float* weight_out= (const float*)d_in[2];
    const float* bias      = (const float*)d_in[3];
    const float* scale_in  = (const float*)d_in[4];
    const float* scale_out = (const float*)d_in[5];
    float* out = (float*)d_out;

    const int M = in_sizes[0] / IN_F;  // 8192

    // 1) weight prep
    {
        int total_groups = (RANK * IN_F + OUT_F * RANK) / 4;  // 131072
        prep_weights_kernel<<<(total_groups + 255) / 256, 256>>>(
            weight_in, weight_out, scale_in, scale_out);
    }

    // 2) GEMM1 -> xp (f16)
    {
        size_t smem = 2 * G1_BM * G1_LDA * sizeof(__half);  // 18432 B (>= Cs reuse)
        gemm1_kernel<<<M / G1_BM, 256, smem>>>(x, M);
    }

    // 3) GEMM2 -> out (f32, bias + 1/rank scaling)
    {
        size_t smem_tiles = (size_t)(G2_BM + G2_BN) * G2_LD * sizeof(__half); // 27648
        size_t smem_c     = (size_t)G2_BM * G2_LDC * sizeof(float);           // 33792
        size_t smem = smem_tiles > smem_c ? smem_tiles : smem_c;
        dim3 grid(M / G2_BM, OUT_F / G2_BN);
        gemm2_kernel<<<grid, 256, smem>>>(bias, out, M);
    }
}

// round 2
// speedup vs baseline: 1.1352x; 1.1352x over previous
#include <cuda_runtime.h>
#include <cuda_fp16.h>
#include <mma.h>

using namespace nvcuda;

#define IN_F   4096
#define OUT_F  4096
#define RANK   64

__device__ __half g_win[RANK * IN_F];    // soft-thresholded, scaled weight_in  [64][4096]
__device__ __half g_wout[OUT_F * RANK];  // soft-thresholded, scaled weight_out [4096][64]
__device__ __half g_xp[8192 * RANK];     // intermediate xp (f16, matching reference cast)

// ---------------------------------------------------------------------------
// Weight prep: 2:4 soft threshold along last dim (groups of 4) + scale + f16
// ---------------------------------------------------------------------------
__device__ __forceinline__ void soft_threshold4(float4 w, float s,
                                                float& o0, float& o1, float& o2, float& o3) {
    float m0 = fabsf(w.x), m1 = fabsf(w.y), m2 = fabsf(w.z), m3 = fabsf(w.w);
    float lo01 = fminf(m0, m1), hi01 = fmaxf(m0, m1);
    float lo23 = fminf(m2, m3), hi23 = fmaxf(m2, m3);
    float t = fminf(fmaxf(lo01, lo23), fminf(hi01, hi23));  // 2nd-smallest
    o0 = copysignf(fmaxf(m0 - t, 0.0f), w.x) * s;
    o1 = copysignf(fmaxf(m1 - t, 0.0f), w.y) * s;
    o2 = copysignf(fmaxf(m2 - t, 0.0f), w.z) * s;
    o3 = copysignf(fmaxf(m3 - t, 0.0f), w.w) * s;
}

__global__ void prep_weights_kernel(const float* __restrict__ win,
                                    const float* __restrict__ wout,
                                    const float* __restrict__ scale_in,
                                    const float* __restrict__ scale_out) {
    const int NGI = RANK * IN_F / 4;
    const int NGO = OUT_F * RANK / 4;
    int idx = blockIdx.x * blockDim.x + threadIdx.x;
    if (idx < NGI) {
        float4 w = reinterpret_cast<const float4*>(win)[idx];
        float o0, o1, o2, o3;
        soft_threshold4(w, *scale_in, o0, o1, o2, o3);
        __half2* dst = reinterpret_cast<__half2*>(g_win) + idx * 2;
        dst[0] = __floats2half2_rn(o0, o1);
        dst[1] = __floats2half2_rn(o2, o3);
    } else if (idx < NGI + NGO) {
        int j = idx - NGI;
        float4 w = reinterpret_cast<const float4*>(wout)[j];
        float o0, o1, o2, o3;
        soft_threshold4(w, *scale_out, o0, o1, o2, o3);
        __half2* dst = reinterpret_cast<__half2*>(g_wout) + j * 2;
        dst[0] = __floats2half2_rn(o0, o1);
        dst[1] = __floats2half2_rn(o2, o3);
    }
}

// ---------------------------------------------------------------------------
// GEMM1: xp[m, r] = sum_k f16(x[m,k]) * g_win[r,k]   (M=8192, N=64, K=4096)
// Block tile 64(M) x 64(N), BK=128: 48KB/CTA in flight during MMA to cover
// DRAM latency. 8 warps (4x2), warp tile 16x32. 32 K-iterations.
// ---------------------------------------------------------------------------
#define G1_BM 64
#define G1_BK 128
#define G1_LDA 136  // half, padded
#define G1_LDC 68   // float, padded

__global__ __launch_bounds__(256, 1)
void gemm1_kernel(const float* __restrict__ x, int M) {
    extern __shared__ char smem_raw[];
    __half* As = reinterpret_cast<__half*>(smem_raw);   // [64][136]
    __half* Bs = As + G1_BM * G1_LDA;                   // [64][136]
    float*  Cs = reinterpret_cast<float*>(smem_raw);    // [64][68] (reuse)

    const int tid  = threadIdx.x;
    const int warp = tid >> 5;
    const int wm   = warp & 3;   // 16 rows each
    const int wn   = warp >> 2;  // 32 cols each
    const int m0   = blockIdx.x * G1_BM;

    wmma::fragment<wmma::accumulator, 16, 16, 16, float> acc[2];
    wmma::fill_fragment(acc[0], 0.0f);
    wmma::fill_fragment(acc[1], 0.0f);

    const int NK = IN_F / G1_BK;  // 32

    float4 xa[8];   // 64x128 f32 tile: 2048 float4 / 256 thr = 8
    int4   wb[4];   // 64x128 f16 tile: 1024 int4  / 256 thr = 4

    auto load_regs = [&](int kt) {
        #pragma unroll
        for (int it = 0; it < 8; it++) {
            int i   = tid + it * 256;
            int row = i >> 5;            // 32 float4 per row of 128 floats
            int c4  = i & 31;
            xa[it] = *reinterpret_cast<const float4*>(
                &x[(size_t)(m0 + row) * IN_F + kt * G1_BK + c4 * 4]);
        }
        #pragma unroll
        for (int it = 0; it < 4; it++) {
            int i   = tid + it * 256;
            int row = i >> 4;            // 16 int4 per row of 128 halves
            int c8  = i & 15;
            wb[it] = *reinterpret_cast<const int4*>(
                &g_win[row * IN_F + kt * G1_BK + c8 * 8]);
        }
    };

    load_regs(0);

    for (int kt = 0; kt < NK; kt++) {
        // stage regs -> smem (convert x to f16 here)
        #pragma unroll
        for (int it = 0; it < 8; it++) {
            int i   = tid + it * 256;
            int row = i >> 5;
            int c4  = i & 31;
            __half* p = &As[row * G1_LDA + c4 * 4];
            reinterpret_cast<__half2*>(p)[0] = __floats2half2_rn(xa[it].x, xa[it].y);
            reinterpret_cast<__half2*>(p)[1] = __floats2half2_rn(xa[it].z, xa[it].w);
        }
        #pragma unroll
        for (int it = 0; it < 4; it++) {
            int i   = tid + it * 256;
            int row = i >> 4;
            int c8  = i & 15;
            *reinterpret_cast<int4*>(&Bs[row * G1_LDA + c8 * 8]) = wb[it];
        }
        __syncthreads();

        if (kt + 1 < NK) load_regs(kt + 1);  // in flight during MMA below

        #pragma unroll
        for (int k4 = 0; k4 < 8; k4++) {
            wmma::fragment<wmma::matrix_a, 16, 16, 16, __half, wmma::row_major> a;
            wmma::load_matrix_sync(a, &As[(wm * 16) * G1_LDA + k4 * 16], G1_LDA);
            #pragma unroll
            for (int j = 0; j < 2; j++) {
                wmma::fragment<wmma::matrix_b, 16, 16, 16, __half, wmma::col_major> b;
                wmma::load_matrix_sync(b, &Bs[(wn * 32 + j * 16) * G1_LDA + k4 * 16], G1_LDA);
                wmma::mma_sync(acc[j], a, b, acc[j]);
            }
        }
        __syncthreads();
    }

    #pragma unroll
    for (int j = 0; j < 2; j++)
        wmma::store_matrix_sync(&Cs[(wm * 16) * G1_LDC + wn * 32 + j * 16], acc[j],
                                G1_LDC, wmma::mem_row_major);
    __syncthreads();

    #pragma unroll
    for (int it = 0; it < 8; it++) {         // 64x32 half2 = 2048 / 256 thr
        int i   = tid + it * 256;
        int row = i >> 5;
        int c2  = i & 31;
        __half2 h = __floats2half2_rn(Cs[row * G1_LDC + c2 * 2],
                                      Cs[row * G1_LDC + c2 * 2 + 1]);
        reinterpret_cast<__half2*>(g_xp)[(size_t)(m0 + row) * (RANK / 2) + c2] = h;
    }
}

// ---------------------------------------------------------------------------
// GEMM2: out[m, o] = (sum_r xp[m,r] * g_wout[o,r] + bias[o]) / 64
// Block tile 128(M) x 128(N), K=64. 8 warps (4x2), warp tile 32x64.
// C staged through smem in two 64-column phases to cap smem at 36KB.
// ---------------------------------------------------------------------------
#define G2_BM 128
#define G2_BN 128
#define G2_LD 72    // half, padded
#define G2_LDC 68   // float, padded (64-col phase)

__global__ __launch_bounds__(256, 1)
void gemm2_kernel(const float* __restrict__ bias, float* __restrict__ out, int M) {
    extern __shared__ char smem_raw[];
    __half* Ps = reinterpret_cast<__half*>(smem_raw);    // xp tile   [128][72]
    __half* Ws = Ps + G2_BM * G2_LD;                     // wout tile [128][72]
    float*  Cs = reinterpret_cast<float*>(smem_raw);     // [128][68] (reuse)

    const int tid  = threadIdx.x;
    const int warp = tid >> 5;
    const int wm   = warp & 3;   // 32 rows each
    const int wn   = warp >> 2;  // 64 cols each
    const int m0   = blockIdx.x * G2_BM;
    const int n0   = blockIdx.y * G2_BN;

    // xp tile: 128 rows x 8 int4 = 1024 int4
    #pragma unroll
    for (int it = 0; it < 4; it++) {
        int i = tid + it * 256;
        int row = i >> 3, c8 = i & 7;
        *reinterpret_cast<int4*>(&Ps[row * G2_LD + c8 * 8]) =
            *reinterpret_cast<const int4*>(&g_xp[(size_t)(m0 + row) * RANK + c8 * 8]);
    }
    // wout tile: 128 rows x 8 int4 = 1024 int4
    #pragma unroll
    for (int it = 0; it < 4; it++) {
        int i = tid + it * 256;
        int row = i >> 3, c8 = i & 7;
        *reinterpret_cast<int4*>(&Ws[row * G2_LD + c8 * 8]) =
            *reinterpret_cast<const int4*>(&g_wout[(size_t)(n0 + row) * RANK + c8 * 8]);
    }
    __syncthreads();

    wmma::fragment<wmma::accumulator, 16, 16, 16, float> acc[2][4];
    #pragma unroll
    for (int i = 0; i < 2; i++)
        #pragma unroll
        for (int j = 0; j < 4; j++) wmma::fill_fragment(acc[i][j], 0.0f);

    #pragma unroll
    for (int k4 = 0; k4 < 4; k4++) {
        wmma::fragment<wmma::matrix_a, 16, 16, 16, __half, wmma::row_major> a[2];
        #pragma unroll
        for (int i = 0; i < 2; i++)
            wmma::load_matrix_sync(a[i], &Ps[(wm * 32 + i * 16) * G2_LD + k4 * 16], G2_LD);
        #pragma unroll
        for (int j = 0; j < 4; j++) {
            wmma::fragment<wmma::matrix_b, 16, 16, 16, __half, wmma::col_major> b;
            wmma::load_matrix_sync(b, &Ws[(wn * 64 + j * 16) * G2_LD + k4 * 16], G2_LD);
            #pragma unroll
            for (int i = 0; i < 2; i++)
                wmma::mma_sync(acc[i][j], a[i], b, acc[i][j]);
        }
    }
    __syncthreads();  // done reading Ps/Ws; Cs aliases them

    const float scaling = 1.0f / (float)RANK;

    #pragma unroll
    for (int ph = 0; ph < 2; ph++) {
        if (wn == ph) {
            #pragma unroll
            for (int i = 0; i < 2; i++)
                #pragma unroll
                for (int j = 0; j < 4; j++)
                    wmma::store_matrix_sync(&Cs[(wm * 32 + i * 16) * G2_LDC + j * 16],
                                            acc[i][j], G2_LDC, wmma::mem_row_major);
        }
        __syncthreads();

        // write 128 x 64 f32 = 2048 float4
        #pragma unroll
        for (int it = 0; it < 8; it++) {
            int i   = tid + it * 256;
            int row = i >> 4;
            int c4  = i & 15;
            float4 c  = *reinterpret_cast<float4*>(&Cs[row * G2_LDC + c4 * 4]);
            float4 bv = *reinterpret_cast<const float4*>(&bias[n0 + ph * 64 + c4 * 4]);
            float4 o;
            o.x = (c.x + bv.x) * scaling;
            o.y = (c.y + bv.y) * scaling;
            o.z = (c.z + bv.z) * scaling;
            o.w = (c.w + bv.w) * scaling;
            *reinterpret_cast<float4*>(
                &out[(size_t)(m0 + row) * OUT_F + n0 + ph * 64 + c4 * 4]) = o;
        }
        __syncthreads();
    }
}

// ---------------------------------------------------------------------------
// Launcher
// ---------------------------------------------------------------------------
extern "C" void kernel_launch(void* const* d_in, const int* in_sizes, int n_in,
                              void* d_out, int out_size) {
    const float* x         = (const float*)d_in[0];
    const float* weight_in = (const float*)d_in[1];
    const float* weight_out= (const float*)d_in[2];
    const float* bias      = (const float*)d_in[3];
    const float* scale_in  = (const float*)d_in[4];
    const float* scale_out = (const float*)d_in[5];
    float* out = (float*)d_out;

    const int M = in_sizes[0] / IN_F;  // 8192

    {
        int total_groups = (RANK * IN_F + OUT_F * RANK) / 4;
        prep_weights_kernel<<<(total_groups + 255) / 256, 256>>>(
            weight_in, weight_out, scale_in, scale_out);
    }
    {
        size_t smem = 2 * (size_t)G1_BM * G1_LDA * sizeof(__half);  // 34816
        gemm1_kernel<<<M / G1_BM, 256, smem>>>(x, M);
    }
    {
        size_t smem_tiles = 2 * (size_t)G2_BM * G2_LD * sizeof(__half);   // 36864
        size_t smem_c     = (size_t)G2_BM * G2_LDC * sizeof(float);        // 34816
        size_t smem = smem_tiles > smem_c ? smem_tiles : smem_c;
        dim3 grid(M / G2_BM, OUT_F / G2_BN);
        gemm2_kernel<<<grid, 256, smem>>>(bias, out, M);
    }
}

// round 3
// speedup vs baseline: 1.4775x; 1.3015x over previous
#include <cuda_runtime.h>
#include <cuda_fp16.h>
#include <mma.h>

using namespace nvcuda;

#define IN_F     4096
#define OUT_F    4096
#define RANK     64
#define RANK_EXT 80   // 64 + 16 ext cols (col 64 = bias term, 65..79 = 0)

__device__ __half g_win [RANK * IN_F];        // [64][4096] f16
__device__ __half g_wout[OUT_F * RANK_EXT];   // [4096][80] f16 (col64=bias)
__device__ __half g_xp  [8192 * RANK_EXT];    // [8192][80] f16 (col64=1.0)

// ---------------------------------------------------------------------------
// helpers
// ---------------------------------------------------------------------------
__device__ __forceinline__ void cp_async16(void* smem_dst, const void* gsrc) {
    unsigned s = (unsigned)__cvta_generic_to_shared(smem_dst);
    asm volatile("cp.async.cg.shared.global [%0], [%1], 16;\n" :: "r"(s), "l"(gsrc));
}
__device__ __forceinline__ void cp_async_commit() {
    asm volatile("cp.async.commit_group;\n");
}
__device__ __forceinline__ void cp_async_wait_all() {
    asm volatile("cp.async.wait_group 0;\n");
}

__device__ __forceinline__ void soft_threshold4(float4 w, float s,
                                                float& o0, float& o1, float& o2, float& o3) {
    float m0 = fabsf(w.x), m1 = fabsf(w.y), m2 = fabsf(w.z), m3 = fabsf(w.w);
    float lo01 = fminf(m0, m1), hi01 = fmaxf(m0, m1);
    float lo23 = fminf(m2, m3), hi23 = fmaxf(m2, m3);
    float t = fminf(fmaxf(lo01, lo23), fminf(hi01, hi23));  // 2nd-smallest
    o0 = copysignf(fmaxf(m0 - t, 0.0f), w.x) * s;
    o1 = copysignf(fmaxf(m1 - t, 0.0f), w.y) * s;
    o2 = copysignf(fmaxf(m2 - t, 0.0f), w.z) * s;
    o3 = copysignf(fmaxf(m3 - t, 0.0f), w.w) * s;
}

// ---------------------------------------------------------------------------
// Weight prep: threshold+scale -> g_win, g_wout(+bias ext col)
// ---------------------------------------------------------------------------
__global__ void prep_weights_kernel(const float* __restrict__ win,
                                    const float* __restrict__ wout,
                                    const float* __restrict__ bias,
                                    const float* __restrict__ scale_in,
                                    const float* __restrict__ scale_out) {
    const int NGI = RANK * IN_F / 4;    // 65536
    const int NGO = OUT_F * RANK / 4;   // 65536
    int idx = blockIdx.x * blockDim.x + threadIdx.x;
    if (idx < NGI) {
        float4 w = reinterpret_cast<const float4*>(win)[idx];
        float o0, o1, o2, o3;
        soft_threshold4(w, __ldg(scale_in), o0, o1, o2, o3);
        __half2* dst = reinterpret_cast<__half2*>(g_win) + idx * 2;
        dst[0] = __floats2half2_rn(o0, o1);
        dst[1] = __floats2half2_rn(o2, o3);
    } else if (idx < NGI + NGO) {
        int j = idx - NGI;
        int o = j >> 4;       // row (16 groups of 4 per 64-col row)
        int c = j & 15;
        float4 w = reinterpret_cast<const float4*>(wout)[j];
        float o0, o1, o2, o3;
        soft_threshold4(w, __ldg(scale_out), o0, o1, o2, o3);
        __half2* dst = reinterpret_cast<__half2*>(g_wout + o * RANK_EXT + c * 4);
        dst[0] = __floats2half2_rn(o0, o1);
        dst[1] = __floats2half2_rn(o2, o3);
    } else if (idx < NGI + NGO + OUT_F) {
        int r = idx - NGI - NGO;
        __half2* d = reinterpret_cast<__half2*>(g_wout + r * RANK_EXT + RANK);
        d[0] = __halves2half2(__float2half(bias[r]), __float2half(0.0f));
        #pragma unroll
        for (int i = 1; i < 8; i++) d[i] = __half2half2(__float2half(0.0f));
    }
}

// ---------------------------------------------------------------------------
// GEMM1: xp[m,r] = sum_k f16(x[m,k]) * g_win[r,k]   (M=8192, N=64, K=4096)
// BM=64, BK=128. Double-buffered smem, 2-deep register prefetch, 1 barrier/iter.
// ---------------------------------------------------------------------------
#define G1_LDA 136  // half, padded
#define G1_LDC 68   // float, padded

__global__ __launch_bounds__(256, 1)
void gemm1_kernel(const float* __restrict__ x) {
    extern __shared__ __half sm1[];
    __half* A0 = sm1;                    // [64][136]
    __half* A1 = sm1 + 64 * G1_LDA;
    __half* B0 = sm1 + 2 * 64 * G1_LDA;
    __half* B1 = sm1 + 3 * 64 * G1_LDA;
    float*  Cs = reinterpret_cast<float*>(sm1);   // aliases A0 (disjoint from A1/B1)

    const int tid  = threadIdx.x;
    const int warp = tid >> 5;
    const int wm   = warp & 3;   // 16 rows
    const int wn   = warp >> 2;  // 32 cols
    const int m0   = blockIdx.x * 64;

    wmma::fragment<wmma::accumulator, 16, 16, 16, float> acc[2];
    wmma::fill_fragment(acc[0], 0.0f);
    wmma::fill_fragment(acc[1], 0.0f);

    const int NK = IN_F / 128;  // 32 (even)

    float4 xa0[8], xa1[8];
    int4   wb0[4], wb1[4];

    auto ldx = [&](float4* xa, int kt) {
        #pragma unroll
        for (int it = 0; it < 8; it++) {
            int i = tid + it * 256;
            int row = i >> 5, c4 = i & 31;       // 32 float4 per 128-f32 row
            xa[it] = __ldcs(reinterpret_cast<const float4*>(
                &x[(size_t)(m0 + row) * IN_F + kt * 128 + c4 * 4]));
        }
    };
    auto ldw = [&](int4* wb, int kt) {
        #pragma unroll
        for (int it = 0; it < 4; it++) {
            int i = tid + it * 256;
            int row = i >> 4, c8 = i & 15;       // 16 int4 per 128-half row
            wb[it] = *reinterpret_cast<const int4*>(
                &g_win[row * IN_F + kt * 128 + c8 * 8]);
        }
    };
    auto stage = [&](__half* A, __half* B, const float4* xa, const int4* wb) {
        #pragma unroll
        for (int it = 0; it < 8; it++) {
            int i = tid + it * 256;
            int row = i >> 5, c4 = i & 31;
            __half* p = &A[row * G1_LDA + c4 * 4];
            reinterpret_cast<__half2*>(p)[0] = __floats2half2_rn(xa[it].x, xa[it].y);
            reinterpret_cast<__half2*>(p)[1] = __floats2half2_rn(xa[it].z, xa[it].w);
        }
        #pragma unroll
        for (int it = 0; it < 4; it++) {
            int i = tid + it * 256;
            int row = i >> 4, c8 = i & 15;
            *reinterpret_cast<int4*>(&B[row * G1_LDA + c8 * 8]) = wb[it];
        }
    };
    auto mma = [&](const __half* A, const __half* B) {
        #pragma unroll
        for (int k4 = 0; k4 < 8; k4++) {
            wmma::fragment<wmma::matrix_a, 16, 16, 16, __half, wmma::row_major> a;
            wmma::load_matrix_sync(a, &A[(wm * 16) * G1_LDA + k4 * 16], G1_LDA);
            #pragma unroll
            for (int j = 0; j < 2; j++) {
                wmma::fragment<wmma::matrix_b, 16, 16, 16, __half, wmma::col_major> b;
                wmma::load_matrix_sync(b, &B[(wn * 32 + j * 16) * G1_LDA + k4 * 16], G1_LDA);
                wmma::mma_sync(acc[j], a, b, acc[j]);
            }
        }
    };

    ldx(xa0, 0); ldw(wb0, 0);
    ldx(xa1, 1); ldw(wb1, 1);

    for (int kt = 0; kt < NK; kt += 2) {
        // slot 0
        stage(A0, B0, xa0, wb0);
        __syncthreads();
        if (kt + 2 < NK) { ldx(xa0, kt + 2); ldw(wb0, kt + 2); }
        mma(A0, B0);
        // slot 1
        stage(A1, B1, xa1, wb1);
        __syncthreads();
        if (kt + 3 < NK) { ldx(xa1, kt + 3); ldw(wb1, kt + 3); }
        mma(A1, B1);
    }
    __syncthreads();

    // epilogue: acc -> Cs (f32) -> g_xp (f16, row stride 80) + ext cols
    #pragma unroll
    for (int j = 0; j < 2; j++)
        wmma::store_matrix_sync(&Cs[(wm * 16) * G1_LDC + wn * 32 + j * 16], acc[j],
                                G1_LDC, wmma::mem_row_major);
    __syncthreads();

    #pragma unroll
    for (int it = 0; it < 8; it++) {
        int i = tid + it * 256;
        int row = i >> 5, c2 = i & 31;
        __half2 h = __floats2half2_rn(Cs[row * G1_LDC + c2 * 2],
                                      Cs[row * G1_LDC + c2 * 2 + 1]);
        reinterpret_cast<__half2*>(g_xp)[(size_t)(m0 + row) * (RANK_EXT / 2) + c2] = h;
    }
    if (tid < 64) {
        __half2* d = reinterpret_cast<__half2*>(g_xp + (size_t)(m0 + tid) * RANK_EXT + RANK);
        d[0] = __halves2half2(__float2half(1.0f), __float2half(0.0f));
        #pragma unroll
        for (int i = 1; i < 8; i++) d[i] = __half2half2(__float2half(0.0f));
    }
}

// ---------------------------------------------------------------------------
// GEMM2: out[m,o] = (xp_ext[m,:] . wout_ext[o,:]) / 64   (K=80 incl. bias col)
// BM=128, BN=128. cp.async tile loads, fragment-scaled, direct gmem store.
// ---------------------------------------------------------------------------
#define G2_LD 88  // half, padded

__global__ __launch_bounds__(256, 2)
void gemm2_kernel(float* __restrict__ out) {
    extern __shared__ __half sm2[];
    __half* Ps = sm2;               // [128][88]
    __half* Ws = sm2 + 128 * G2_LD; // [128][88]

    const int tid  = threadIdx.x;
    const int warp = tid >> 5;
    const int wm   = warp & 3;   // 32 rows
    const int wn   = warp >> 2;  // 64 cols
    const int m0   = blockIdx.x * 128;
    const int n0   = blockIdx.y * 128;

    // 128 rows x 10 16B-chunks each, for Ps and Ws
    #pragma unroll
    for (int it = 0; it < 5; it++) {
        int c = tid + it * 256;
        int row = c / 10, off = c % 10;
        cp_async16(Ps + row * G2_LD + off * 8,
                   g_xp + (size_t)(m0 + row) * RANK_EXT + off * 8);
    }
    #pragma unroll
    for (int it = 0; it < 5; it++) {
        int c = tid + it * 256;
        int row = c / 10, off = c % 10;
        cp_async16(Ws + row * G2_LD + off * 8,
                   g_wout + (size_t)(n0 + row) * RANK_EXT + off * 8);
    }
    cp_async_commit();
    cp_async_wait_all();
    __syncthreads();

    wmma::fragment<wmma::accumulator, 16, 16, 16, float> acc[2][4];
    #pragma unroll
    for (int i = 0; i < 2; i++)
        #pragma unroll
        for (int j = 0; j < 4; j++) wmma::fill_fragment(acc[i][j], 0.0f);

    #pragma unroll
    for (int k4 = 0; k4 < 5; k4++) {   // K = 80
        wmma::fragment<wmma::matrix_a, 16, 16, 16, __half, wmma::row_major> a[2];
        #pragma unroll
        for (int i = 0; i < 2; i++)
            wmma::load_matrix_sync(a[i], &Ps[(wm * 32 + i * 16) * G2_LD + k4 * 16], G2_LD);
        #pragma unroll
        for (int j = 0; j < 4; j++) {
            wmma::fragment<wmma::matrix_b, 16, 16, 16, __half, wmma::col_major> b;
            wmma::load_matrix_sync(b, &Ws[(wn * 64 + j * 16) * G2_LD + k4 * 16], G2_LD);
            #pragma unroll
            for (int i = 0; i < 2; i++)
                wmma::mma_sync(acc[i][j], a[i], b, acc[i][j]);
        }
    }

    const float scaling = 1.0f / (float)RANK;
    #pragma unroll
    for (int i = 0; i < 2; i++)
        #pragma unroll
        for (int j = 0; j < 4; j++) {
            #pragma unroll
            for (int e = 0; e < acc[i][j].num_elements; e++)
                acc[i][j].x[e] *= scaling;
            wmma::store_matrix_sync(
                &out[(size_t)(m0 + wm * 32 + i * 16) * OUT_F + n0 + wn * 64 + j * 16],
                acc[i][j], OUT_F, wmma::mem_row_major);
        }
}

// ---------------------------------------------------------------------------
// Launcher
// ---------------------------------------------------------------------------
extern "C" void kernel_launch(void* const* d_in, const int* in_sizes, int n_in,
                              void* d_out, int out_size) {
    const float* x         = (const float*)d_in[0];
    const float* weight_in = (const float*)d_in[1];
    const float* weight_out= (const float*)d_in[2];
    const float* bias      = (const float*)d_in[3];
    const float* scale_in  = (const float*)d_in[4];
    const float* scale_out = (const float*)d_in[5];
    float* out = (float*)d_out;

    const int M = in_sizes[0] / IN_F;  // 8192

    {
        int total = RANK * IN_F / 4 + OUT_F * RANK / 4 + OUT_F;  // 135168
        prep_weights_kernel<<<(total + 255) / 256, 256>>>(
            weight_in, weight_out, bias, scale_in, scale_out);
    }
    {
        size_t smem = 4 * (size_t)64 * G1_LDA * sizeof(__half);  // 69632
        static bool attr1 = false;
        cudaFuncSetAttribute(gemm1_kernel,
                             cudaFuncAttributeMaxDynamicSharedMemorySize, (int)smem);
        (void)attr1;
        gemm1_kernel<<<M / 64, 256, smem>>>(x);
    }
    {
        size_t smem = 2 * (size_t)128 * G2_LD * sizeof(__half);  // 45056
        dim3 grid(M / 128, OUT_F / 128);
        gemm2_kernel<<<grid, 256, smem>>>(out);
    }
}

// round 4
// speedup vs baseline: 1.5142x; 1.0248x over previous
#include <cuda_runtime.h>
#include <cuda_fp16.h>
#include <mma.h>

using namespace nvcuda;

#define IN_F     4096
#define OUT_F    4096
#define RANK     64
#define RANK_EXT 80   // 64 + 16 ext cols (col 64 = bias term, 65..79 = 0)
#define M_ROWS   8192

__device__ __half g_win [RANK * IN_F];          // [64][4096] f16
__device__ __half g_wout[OUT_F * RANK_EXT];     // [4096][80] f16 (col64=bias)
__device__ __half g_xp  [M_ROWS * RANK_EXT];    // [8192][80] f16 (col64=1.0)
__device__ float  g_xp32[2 * M_ROWS * RANK];    // K-split partials, f32

// ---------------------------------------------------------------------------
// helpers
// ---------------------------------------------------------------------------
__device__ __forceinline__ void cp_async16(void* smem_dst, const void* gsrc) {
    unsigned s = (unsigned)__cvta_generic_to_shared(smem_dst);
    asm volatile("cp.async.cg.shared.global [%0], [%1], 16;\n" :: "r"(s), "l"(gsrc));
}
__device__ __forceinline__ void cp_async_commit() {
    asm volatile("cp.async.commit_group;\n");
}
__device__ __forceinline__ void cp_async_wait_all() {
    asm volatile("cp.async.wait_group 0;\n");
}

__device__ __forceinline__ void soft_threshold4(float4 w, float s,
                                                float& o0, float& o1, float& o2, float& o3) {
    float m0 = fabsf(w.x), m1 = fabsf(w.y), m2 = fabsf(w.z), m3 = fabsf(w.w);
    float lo01 = fminf(m0, m1), hi01 = fmaxf(m0, m1);
    float lo23 = fminf(m2, m3), hi23 = fmaxf(m2, m3);
    float t = fminf(fmaxf(lo01, lo23), fminf(hi01, hi23));  // 2nd-smallest
    o0 = copysignf(fmaxf(m0 - t, 0.0f), w.x) * s;
    o1 = copysignf(fmaxf(m1 - t, 0.0f), w.y) * s;
    o2 = copysignf(fmaxf(m2 - t, 0.0f), w.z) * s;
    o3 = copysignf(fmaxf(m3 - t, 0.0f), w.w) * s;
}

// ---------------------------------------------------------------------------
// Weight prep: threshold+scale -> g_win, g_wout(+bias ext col)
// ---------------------------------------------------------------------------
__global__ void prep_weights_kernel(const float* __restrict__ win,
                                    const float* __restrict__ wout,
                                    const float* __restrict__ bias,
                                    const float* __restrict__ scale_in,
                                    const float* __restrict__ scale_out) {
    const int NGI = RANK * IN_F / 4;    // 65536
    const int NGO = OUT_F * RANK / 4;   // 65536
    int idx = blockIdx.x * blockDim.x + threadIdx.x;
    if (idx < NGI) {
        float4 w = reinterpret_cast<const float4*>(win)[idx];
        float o0, o1, o2, o3;
        soft_threshold4(w, __ldg(scale_in), o0, o1, o2, o3);
        __half2* dst = reinterpret_cast<__half2*>(g_win) + idx * 2;
        dst[0] = __floats2half2_rn(o0, o1);
        dst[1] = __floats2half2_rn(o2, o3);
    } else if (idx < NGI + NGO) {
        int j = idx - NGI;
        int o = j >> 4;       // row (16 groups of 4 per 64-col row)
        int c = j & 15;
        float4 w = reinterpret_cast<const float4*>(wout)[j];
        float o0, o1, o2, o3;
        soft_threshold4(w, __ldg(scale_out), o0, o1, o2, o3);
        __half2* dst = reinterpret_cast<__half2*>(g_wout + o * RANK_EXT + c * 4);
        dst[0] = __floats2half2_rn(o0, o1);
        dst[1] = __floats2half2_rn(o2, o3);
    } else if (idx < NGI + NGO + OUT_F) {
        int r = idx - NGI - NGO;
        __half2* d = reinterpret_cast<__half2*>(g_wout + r * RANK_EXT + RANK);
        d[0] = __halves2half2(__float2half(bias[r]), __float2half(0.0f));
        #pragma unroll
        for (int i = 1; i < 8; i++) d[i] = __half2half2(__float2half(0.0f));
    }
}

// ---------------------------------------------------------------------------
// GEMM1 (K-split x2): xp32[ks][m,r] = sum_{k in half ks} f16(x[m,k])*g_win[r,k]
// BM=64, BK=64, grid (128, 2) = 256 CTAs, 2 CTAs/SM. Double-buffered smem,
// 2-deep register prefetch, one barrier per slot. Direct f32 store to gmem.
// ---------------------------------------------------------------------------
#define G1_LDA 72   // half, padded

__global__ __launch_bounds__(256, 2)
void gemm1_kernel(const float* __restrict__ x) {
    extern __shared__ __half sm1[];
    __half* A0 = sm1;                   // [64][72]
    __half* A1 = sm1 + 64 * G1_LDA;
    __half* B0 = sm1 + 2 * 64 * G1_LDA;
    __half* B1 = sm1 + 3 * 64 * G1_LDA;

    const int tid  = threadIdx.x;
    const int warp = tid >> 5;
    const int wm   = warp & 3;   // 16 rows
    const int wn   = warp >> 2;  // 32 cols
    const int m0   = blockIdx.x * 64;
    const int ks   = blockIdx.y;         // K half: 0 or 1
    const int k0   = ks * (IN_F / 2);    // 0 or 2048

    wmma::fragment<wmma::accumulator, 16, 16, 16, float> acc[2];
    wmma::fill_fragment(acc[0], 0.0f);
    wmma::fill_fragment(acc[1], 0.0f);

    const int NK = (IN_F / 2) / 64;  // 32 (even)

    float4 xa0[4], xa1[4];
    int4   wb0[2], wb1[2];

    auto ldx = [&](float4* xa, int kt) {
        #pragma unroll
        for (int it = 0; it < 4; it++) {
            int i = tid + it * 256;
            int row = i >> 4, c4 = i & 15;      // 16 float4 per 64-f32 row
            xa[it] = __ldcs(reinterpret_cast<const float4*>(
                &x[(size_t)(m0 + row) * IN_F + k0 + kt * 64 + c4 * 4]));
        }
    };
    auto ldw = [&](int4* wb, int kt) {
        #pragma unroll
        for (int it = 0; it < 2; it++) {
            int i = tid + it * 256;
            int row = i >> 3, c8 = i & 7;       // 8 int4 per 64-half row
            wb[it] = *reinterpret_cast<const int4*>(
                &g_win[row * IN_F + k0 + kt * 64 + c8 * 8]);
        }
    };
    auto stage = [&](__half* A, __half* B, const float4* xa, const int4* wb) {
        #pragma unroll
        for (int it = 0; it < 4; it++) {
            int i = tid + it * 256;
            int row = i >> 4, c4 = i & 15;
            __half* p = &A[row * G1_LDA + c4 * 4];
            reinterpret_cast<__half2*>(p)[0] = __floats2half2_rn(xa[it].x, xa[it].y);
            reinterpret_cast<__half2*>(p)[1] = __floats2half2_rn(xa[it].z, xa[it].w);
        }
        #pragma unroll
        for (int it = 0; it < 2; it++) {
            int i = tid + it * 256;
            int row = i >> 3, c8 = i & 7;
            *reinterpret_cast<int4*>(&B[row * G1_LDA + c8 * 8]) = wb[it];
        }
    };
    auto mma = [&](const __half* A, const __half* B) {
        #pragma unroll
        for (int k4 = 0; k4 < 4; k4++) {
            wmma::fragment<wmma::matrix_a, 16, 16, 16, __half, wmma::row_major> a;
            wmma::load_matrix_sync(a, &A[(wm * 16) * G1_LDA + k4 * 16], G1_LDA);
            #pragma unroll
            for (int j = 0; j < 2; j++) {
                wmma::fragment<wmma::matrix_b, 16, 16, 16, __half, wmma::col_major> b;
                wmma::load_matrix_sync(b, &B[(wn * 32 + j * 16) * G1_LDA + k4 * 16], G1_LDA);
                wmma::mma_sync(acc[j], a, b, acc[j]);
            }
        }
    };

    ldx(xa0, 0); ldw(wb0, 0);
    ldx(xa1, 1); ldw(wb1, 1);

    for (int kt = 0; kt < NK; kt += 2) {
        stage(A0, B0, xa0, wb0);
        __syncthreads();
        if (kt + 2 < NK) { ldx(xa0, kt + 2); ldw(wb0, kt + 2); }
        mma(A0, B0);

        stage(A1, B1, xa1, wb1);
        __syncthreads();
        if (kt + 3 < NK) { ldx(xa1, kt + 3); ldw(wb1, kt + 3); }
        mma(A1, B1);
    }

    // direct f32 store of partials (row stride 64 floats)
    float* outp = g_xp32 + (size_t)ks * M_ROWS * RANK;
    #pragma unroll
    for (int j = 0; j < 2; j++)
        wmma::store_matrix_sync(&outp[(size_t)(m0 + wm * 16) * RANK + wn * 32 + j * 16],
                                acc[j], RANK, wmma::mem_row_major);
}

// ---------------------------------------------------------------------------
// Combine: g_xp[m][c] = f16(xp32[0][m][c] + xp32[1][m][c]); ext col 64 = 1.0
// ---------------------------------------------------------------------------
__global__ void combine_xp_kernel() {
    int i = blockIdx.x * blockDim.x + threadIdx.x;   // over 8192 * 40 half2 cols
    if (i >= M_ROWS * (RANK_EXT / 2)) return;
    int m  = i / (RANK_EXT / 2);
    int c2 = i % (RANK_EXT / 2);
    __half2 h;
    if (c2 < RANK / 2) {
        const float2* a = reinterpret_cast<const float2*>(g_xp32 + (size_t)m * RANK) + c2;
        const float2* b = reinterpret_cast<const float2*>(g_xp32 + (size_t)(M_ROWS + m) * RANK) + c2;
        float2 av = *a, bv = *b;
        h = __floats2half2_rn(av.x + bv.x, av.y + bv.y);
    } else if (c2 == RANK / 2) {
        h = __halves2half2(__float2half(1.0f), __float2half(0.0f));
    } else {
        h = __half2half2(__float2half(0.0f));
    }
    reinterpret_cast<__half2*>(g_xp)[(size_t)m * (RANK_EXT / 2) + c2] = h;
}

// ---------------------------------------------------------------------------
// GEMM2: out[m,o] = (xp_ext[m,:] . wout_ext[o,:]) / 64   (K=80 incl. bias col)
// BM=128, BN=128. cp.async tile loads, fragment-scaled, direct gmem store.
// ---------------------------------------------------------------------------
#define G2_LD 88  // half, padded

__global__ __launch_bounds__(256, 2)
void gemm2_kernel(float* __restrict__ out) {
    extern __shared__ __half sm2[];
    __half* Ps = sm2;               // [128][88]
    __half* Ws = sm2 + 128 * G2_LD; // [128][88]

    const int tid  = threadIdx.x;
    const int warp = tid >> 5;
    const int wm   = warp & 3;   // 32 rows
    const int wn   = warp >> 2;  // 64 cols
    const int m0   = blockIdx.x * 128;
    const int n0   = blockIdx.y * 128;

    #pragma unroll
    for (int it = 0; it < 5; it++) {
        int c = tid + it * 256;
        int row = c / 10, off = c % 10;
        cp_async16(Ps + row * G2_LD + off * 8,
                   g_xp + (size_t)(m0 + row) * RANK_EXT + off * 8);
    }
    #pragma unroll
    for (int it = 0; it < 5; it++) {
        int c = tid + it * 256;
        int row = c / 10, off = c % 10;
        cp_async16(Ws + row * G2_LD + off * 8,
                   g_wout + (size_t)(n0 + row) * RANK_EXT + off * 8);
    }
    cp_async_commit();
    cp_async_wait_all();
    __syncthreads();

    wmma::fragment<wmma::accumulator, 16, 16, 16, float> acc[2][4];
    #pragma unroll
    for (int i = 0; i < 2; i++)
        #pragma unroll
        for (int j = 0; j < 4; j++) wmma::fill_fragment(acc[i][j], 0.0f);

    #pragma unroll
    for (int k4 = 0; k4 < 5; k4++) {   // K = 80
        wmma::fragment<wmma::matrix_a, 16, 16, 16, __half, wmma::row_major> a[2];
        #pragma unroll
        for (int i = 0; i < 2; i++)
            wmma::load_matrix_sync(a[i], &Ps[(wm * 32 + i * 16) * G2_LD + k4 * 16], G2_LD);
        #pragma unroll
        for (int j = 0; j < 4; j++) {
            wmma::fragment<wmma::matrix_b, 16, 16, 16, __half, wmma::col_major> b;
            wmma::load_matrix_sync(b, &Ws[(wn * 64 + j * 16) * G2_LD + k4 * 16], G2_LD);
            #pragma unroll
            for (int i = 0; i < 2; i++)
                wmma::mma_sync(acc[i][j], a[i], b, acc[i][j]);
        }
    }

    const float scaling = 1.0f / (float)RANK;
    #pragma unroll
    for (int i = 0; i < 2; i++)
        #pragma unroll
        for (int j = 0; j < 4; j++) {
            #pragma unroll
            for (int e = 0; e < acc[i][j].num_elements; e++)
                acc[i][j].x[e] *= scaling;
            wmma::store_matrix_sync(
                &out[(size_t)(m0 + wm * 32 + i * 16) * OUT_F + n0 + wn * 64 + j * 16],
                acc[i][j], OUT_F, wmma::mem_row_major);
        }
}

// ---------------------------------------------------------------------------
// Launcher
// ---------------------------------------------------------------------------
extern "C" void kernel_launch(void* const* d_in, const int* in_sizes, int n_in,
                              void* d_out, int out_size) {
    const float* x         = (const float*)d_in[0];
    const float* weight_in = (const float*)d_in[1];
    const float* weight_out= (const float*)d_in[2];
    const float* bias      = (const float*)d_in[3];
    const float* scale_in  = (const float*)d_in[4];
    const float* scale_out = (const float*)d_in[5];
    float* out = (float*)d_out;

    const int M = in_sizes[0] / IN_F;  // 8192

    {
        int total = RANK * IN_F / 4 + OUT_F * RANK / 4 + OUT_F;  // 135168
        prep_weights_kernel<<<(total + 255) / 256, 256>>>(
            weight_in, weight_out, bias, scale_in, scale_out);
    }
    {
        size_t smem = 4 * (size_t)64 * G1_LDA * sizeof(__half);  // 36864 (<48KB)
        dim3 grid(M / 64, 2);
        gemm1_kernel<<<grid, 256, smem>>>(x);
    }
    {
        int total = M_ROWS * (RANK_EXT / 2);  // 327680
        combine_xp_kernel<<<(total + 255) / 256, 256>>>();
    }
    {
        size_t smem = 2 * (size_t)128 * G2_LD * sizeof(__half);  // 45056
        dim3 grid(M / 128, OUT_F / 128);
        gemm2_kernel<<<grid, 256, smem>>>(out);
    }
}